// round 4
// baseline (speedup 1.0000x reference)
#include <cuda_runtime.h>

#define NN    32768
#define NB    64        // graphs
#define CIN   256
#define E     256
#define NSC   4
#define OS    64        // out per scale
#define NH    8
#define HD    32
#define BN_EPS 1e-5f

// ---------------- scratch (device globals: no allocation allowed) ----------
__device__ float g_h  [(size_t)NN * E];        // 32 MB
__device__ float g_qkv[(size_t)NN * 3 * E];    // 96 MB
__device__ float g_ctx[(size_t)NN * E];        // 32 MB
__device__ float g_att[(size_t)NN * E];        // 32 MB
__device__ int   g_counts[NB];
__device__ int   g_starts[NB];
__device__ int   g_maxM;
__device__ int   g_stride;                     // 1 = int32 batch, 2 = int64 batch
__device__ float g_psum  [256 * E];            // deterministic BN partials
__device__ float g_psumsq[256 * E];
__device__ float g_bnscale[E];
__device__ float g_bnshift[E];

// ---------------- batch bookkeeping ----------------------------------------
// The reference casts batch with jnp.astype(int64); under default JAX config
// (x64 disabled) this silently yields int32. Detect the element width by
// scanning odd 32-bit words: for little-endian int64 values < 2^32 they are
// all zero; for int32 data they are batch[odd] which (sorted ids over 64
// graphs) are mostly nonzero. Reads stay within 4*NN bytes either way.
__global__ void k_detect(const int* __restrict__ b32)
{
    __shared__ int any;
    if (threadIdx.x == 0) any = 0;
    __syncthreads();
    int loc = 0;
    for (int i = threadIdx.x; i < NN / 2; i += blockDim.x)
        if (b32[2 * i + 1] != 0) loc = 1;
    if (loc) atomicExch(&any, 1);
    __syncthreads();
    if (threadIdx.x == 0) {
        g_stride = any ? 1 : 2;
        for (int b = 0; b < NB; b++) g_counts[b] = 0;
    }
}

__global__ void k_hist(const int* __restrict__ b32)
{
    __shared__ int hc[NB];
    int t = threadIdx.x;
    if (t < NB) hc[t] = 0;
    __syncthreads();
    int n = blockIdx.x * blockDim.x + t;
    int v = b32[(size_t)n * g_stride] & (NB - 1);   // clamp for safety
    atomicAdd(&hc[v], 1);
    __syncthreads();
    if (t < NB) atomicAdd(&g_counts[t], hc[t]);
}

__global__ void k_scan()
{
    // B=64 -> single thread is fine
    int run = 0, mx = 0;
    for (int b = 0; b < NB; b++) {
        g_starts[b] = run;
        int c = g_counts[b];
        run += c;
        if (c > mx) mx = c;
    }
    g_maxM = mx;
}

// ---------------- GEMM 1: per-scale linear on (x + spectral) ---------------
// h[n, s*64+o] = sum_i (x[n,i] + spectral[s,n,i]) * Ws[s,i,o] + bs[s,o]
// grid: (NN/64, 1, NSC), block: 256 (16x16, 4x4 micro-tile)
__global__ void k_gemm_scale(const float* __restrict__ x,
                             const float* __restrict__ spec,
                             const float* __restrict__ Ws,
                             const float* __restrict__ bs)
{
    __shared__ float As[16][65];
    __shared__ float Bs[16][65];
    const int s  = blockIdx.z;
    const int m0 = blockIdx.x * 64;
    const int tid = threadIdx.x;
    const int tx = tid & 15, ty = tid >> 4;

    const float* xb = x    + (size_t)m0 * CIN;
    const float* sb = spec + (size_t)s * NN * CIN + (size_t)m0 * CIN;
    const float* Wb = Ws   + (size_t)s * CIN * OS;

    const int lr = tid >> 2;          // 0..63 row within tile
    const int lk = (tid & 3) * 4;     // k offset
    const int bk = tid >> 4;          // 0..15
    const int bo = (tid & 15) * 4;    // 0..60

    float acc[4][4] = {};

    for (int k0 = 0; k0 < CIN; k0 += 16) {
        float4 a  = *(const float4*)(xb + (size_t)lr * CIN + k0 + lk);
        float4 a2 = *(const float4*)(sb + (size_t)lr * CIN + k0 + lk);
        As[lk + 0][lr] = a.x + a2.x;
        As[lk + 1][lr] = a.y + a2.y;
        As[lk + 2][lr] = a.z + a2.z;
        As[lk + 3][lr] = a.w + a2.w;
        float4 b = *(const float4*)(Wb + (size_t)(k0 + bk) * OS + bo);
        Bs[bk][bo + 0] = b.x;
        Bs[bk][bo + 1] = b.y;
        Bs[bk][bo + 2] = b.z;
        Bs[bk][bo + 3] = b.w;
        __syncthreads();
#pragma unroll
        for (int k = 0; k < 16; k++) {
            float av[4], bv[4];
#pragma unroll
            for (int i = 0; i < 4; i++) av[i] = As[k][ty * 4 + i];
#pragma unroll
            for (int j = 0; j < 4; j++) bv[j] = Bs[k][tx * 4 + j];
#pragma unroll
            for (int i = 0; i < 4; i++)
#pragma unroll
                for (int j = 0; j < 4; j++) acc[i][j] += av[i] * bv[j];
        }
        __syncthreads();
    }
#pragma unroll
    for (int i = 0; i < 4; i++) {
        int m = m0 + ty * 4 + i;
#pragma unroll
        for (int j = 0; j < 4; j++) {
            int o = tx * 4 + j;
            g_h[(size_t)m * E + s * OS + o] = acc[i][j] + bs[s * OS + o];
        }
    }
}

// ---------------- GEMM body: C = A[NN,256] * W^T + bias --------------------
// W row-major [Nc, 256]; tile (m0, n0) from blockIdx, 64x64
__device__ __forceinline__ void gemm_wt_body(const float* __restrict__ A,
                                             const float* __restrict__ W,
                                             const float* __restrict__ bias,
                                             float* __restrict__ C, int ldc)
{
    __shared__ float As[16][65];
    __shared__ float Bs[16][65];
    const int m0 = blockIdx.x * 64;
    const int n0 = blockIdx.y * 64;
    const int tid = threadIdx.x;
    const int tx = tid & 15, ty = tid >> 4;
    const int lr = tid >> 2;
    const int lk = (tid & 3) * 4;

    float acc[4][4] = {};

    for (int k0 = 0; k0 < 256; k0 += 16) {
        float4 a = *(const float4*)(A + (size_t)(m0 + lr) * 256 + k0 + lk);
        As[lk + 0][lr] = a.x;
        As[lk + 1][lr] = a.y;
        As[lk + 2][lr] = a.z;
        As[lk + 3][lr] = a.w;
        float4 b = *(const float4*)(W + (size_t)(n0 + lr) * 256 + k0 + lk);
        Bs[lk + 0][lr] = b.x;
        Bs[lk + 1][lr] = b.y;
        Bs[lk + 2][lr] = b.z;
        Bs[lk + 3][lr] = b.w;
        __syncthreads();
#pragma unroll
        for (int k = 0; k < 16; k++) {
            float av[4], bv[4];
#pragma unroll
            for (int i = 0; i < 4; i++) av[i] = As[k][ty * 4 + i];
#pragma unroll
            for (int j = 0; j < 4; j++) bv[j] = Bs[k][tx * 4 + j];
#pragma unroll
            for (int i = 0; i < 4; i++)
#pragma unroll
                for (int j = 0; j < 4; j++) acc[i][j] += av[i] * bv[j];
        }
        __syncthreads();
    }
#pragma unroll
    for (int i = 0; i < 4; i++) {
        int m = m0 + ty * 4 + i;
#pragma unroll
        for (int j = 0; j < 4; j++) {
            int n = n0 + tx * 4 + j;
            C[(size_t)m * ldc + n] = acc[i][j] + bias[n];
        }
    }
}

__global__ void k_gemm_qkv(const float* __restrict__ W, const float* __restrict__ bias)
{
    gemm_wt_body(g_h, W, bias, g_qkv, 3 * E);
}

__global__ void k_gemm_out(const float* __restrict__ W, const float* __restrict__ bias)
{
    gemm_wt_body(g_ctx, W, bias, g_att, E);
}

// ---------------- attention: per (graph, head), online softmax -------------
// Padding semantics of the reference (no key-padding mask): each graph is
// padded to M = max count; padded rows have h=0 -> k_pad = b_in[E:2E],
// v_pad = b_in[2E:3E]. Fold (M-c) copies of that key analytically.
__global__ void k_attn(const float* __restrict__ b_in)
{
    __shared__ float Kt[64][32];
    __shared__ float Vt[64][32];
    __shared__ float kp[32], vp[32];

    const int b = blockIdx.x;
    const int h = blockIdx.y;
    const int tid = threadIdx.x;          // 128 threads
    const int c = g_counts[b];
    const int start = g_starts[b];
    const int M = g_maxM;
    const float qscale = 0.17677669529663687f; // 1/sqrt(32)

    if (tid < 32) {
        kp[tid] = b_in[E     + h * HD + tid];
        vp[tid] = b_in[2 * E + h * HD + tid];
    }
    __syncthreads();

    for (int q0 = 0; q0 < c; q0 += 128) {
        const int qi = q0 + tid;
        const bool valid = qi < c;
        float qv[HD];
        if (valid) {
            const float* qp = g_qkv + (size_t)(start + qi) * 768 + h * HD;
#pragma unroll
            for (int d = 0; d < HD; d++) qv[d] = qp[d] * qscale;
        }
        float m = -1e9f, l = 0.f, acc[HD];
#pragma unroll
        for (int d = 0; d < HD; d++) acc[d] = 0.f;

        for (int kb = 0; kb < c; kb += 64) {
            const int nk = min(64, c - kb);
            __syncthreads();
            for (int e = tid; e < nk * 32; e += 128) {
                int j = e >> 5, d = e & 31;
                size_t base = (size_t)(start + kb + j) * 768 + h * HD + d;
                Kt[j][d] = g_qkv[base + E];
                Vt[j][d] = g_qkv[base + 2 * E];
            }
            __syncthreads();
            if (valid) {
                for (int j = 0; j < nk; j++) {
                    float s = 0.f;
#pragma unroll
                    for (int d = 0; d < HD; d++) s += qv[d] * Kt[j][d];
                    float mn = fmaxf(m, s);
                    float corr = __expf(m - mn);
                    float w = __expf(s - mn);
                    l = l * corr + w;
#pragma unroll
                    for (int d = 0; d < HD; d++) acc[d] = acc[d] * corr + w * Vt[j][d];
                    m = mn;
                }
            }
        }

        if (valid) {
            int npad = M - c;
            if (npad > 0) {
                float s = 0.f;
#pragma unroll
                for (int d = 0; d < HD; d++) s += qv[d] * kp[d];
                float mn = fmaxf(m, s);
                float corr = __expf(m - mn);
                float w = __expf(s - mn) * (float)npad;
                l = l * corr + w;
#pragma unroll
                for (int d = 0; d < HD; d++) acc[d] = acc[d] * corr + w * vp[d];
                m = mn;
            }
            float inv = 1.f / l;
            float* o = g_ctx + (size_t)(start + qi) * E + h * HD;
#pragma unroll
            for (int d = 0; d < HD; d++) o[d] = acc[d] * inv;
        }
    }
}

// ---------------- BatchNorm (training stats) + ReLU -------------------------
// Deterministic two-stage column reduction (no float atomics).
__global__ void k_bn_stats()
{
    const int ch = threadIdx.x;           // 256 channels
    const int r0 = blockIdx.x * 128;      // 256 blocks x 128 rows
    float s = 0.f, s2 = 0.f;
    for (int r = 0; r < 128; r++) {
        float v = g_att[(size_t)(r0 + r) * E + ch];
        s += v;
        s2 += v * v;
    }
    g_psum  [blockIdx.x * E + ch] = s;
    g_psumsq[blockIdx.x * E + ch] = s2;
}

__global__ void k_bn_finalize(const float* __restrict__ gamma,
                              const float* __restrict__ beta)
{
    const int ch = threadIdx.x;
    float s = 0.f, s2 = 0.f;
    for (int p = 0; p < 256; p++) {
        s  += g_psum  [p * E + ch];
        s2 += g_psumsq[p * E + ch];
    }
    float mean = s / (float)NN;
    float var  = s2 / (float)NN - mean * mean;
    float sc = rsqrtf(var + BN_EPS) * gamma[ch];
    g_bnscale[ch] = sc;
    g_bnshift[ch] = beta[ch] - mean * sc;
}

__global__ void k_bn_apply(float* __restrict__ out)
{
    size_t i4 = (size_t)blockIdx.x * blockDim.x + threadIdx.x;   // float4 index
    size_t idx = i4 * 4;
    int ch = (int)(idx & (E - 1));
    float4 v = *(const float4*)(g_att + idx);
    float4 r;
    r.x = fmaxf(v.x * g_bnscale[ch + 0] + g_bnshift[ch + 0], 0.f);
    r.y = fmaxf(v.y * g_bnscale[ch + 1] + g_bnshift[ch + 1], 0.f);
    r.z = fmaxf(v.z * g_bnscale[ch + 2] + g_bnshift[ch + 2], 0.f);
    r.w = fmaxf(v.w * g_bnscale[ch + 3] + g_bnshift[ch + 3], 0.f);
    *(float4*)(out + idx) = r;
}

// ---------------- launch -----------------------------------------------------
extern "C" void kernel_launch(void* const* d_in, const int* in_sizes, int n_in,
                              void* d_out, int out_size)
{
    const float* x        = (const float*)d_in[0];
    const float* spectral = (const float*)d_in[1];
    const float* Ws       = (const float*)d_in[2];
    const float* bs       = (const float*)d_in[3];
    const float* W_in     = (const float*)d_in[4];
    const float* b_in     = (const float*)d_in[5];
    const float* W_out    = (const float*)d_in[6];
    const float* b_out    = (const float*)d_in[7];
    const float* gamma    = (const float*)d_in[8];
    const float* beta     = (const float*)d_in[9];
    const int*   batch32  = (const int*)d_in[10];   // width detected at runtime
    float* out = (float*)d_out;

    k_detect<<<1, 256>>>(batch32);
    k_hist<<<NN / 256, 256>>>(batch32);
    k_scan<<<1, 1>>>();

    k_gemm_scale<<<dim3(NN / 64, 1, NSC), 256>>>(x, spectral, Ws, bs);
    k_gemm_qkv<<<dim3(NN / 64, 12), 256>>>(W_in, b_in);
    k_attn<<<dim3(NB, NH), 128>>>(b_in);
    k_gemm_out<<<dim3(NN / 64, 4), 256>>>(W_out, b_out);

    k_bn_stats<<<256, 256>>>();
    k_bn_finalize<<<1, 256>>>(gamma, beta);
    k_bn_apply<<<(NN * E / 4) / 256, 256>>>(out);
}